// round 10
// baseline (speedup 1.0000x reference)
#include <cuda_runtime.h>
#include <cuda_bf16.h>

#define RADIUS 3
constexpr int N_ = 2, C_ = 64, S_ = 4, H_ = 64, W_ = 44;
constexpr int P_  = H_ * W_;
constexpr int SP_ = S_ * P_;            // channel stride
constexpr int TILE_Y = 4;
constexpr int NTHREADS = 768;           // 24 warps

// Pixel-major bf16 tiles: one pixel = 64 ch * 2B = 128 B row, SW128 swizzled.
constexpr int F1ROWS = 10;              // y0-3 .. y0+6
constexpr int F1PX   = 56;              // n_x in [-3, 52] -> col = n_x + 3
constexpr int F0PX   = 48;
constexpr int OFF_F1HI = 0;
constexpr int OFF_F1LO = OFF_F1HI + F1ROWS * F1PX * 128;   // 71680
constexpr int OFF_F0HI = OFF_F1LO + F1ROWS * F1PX * 128;   // 143360
constexpr int OFF_F0LO = OFF_F0HI + TILE_Y * F0PX * 128;   // 167936
constexpr int OFF_TAPS = OFF_F0LO + TILE_Y * F0PX * 128;   // 192512
constexpr int SMEM_BYTES = OFF_TAPS + 176 * 49 * 4;        // 227008
// epilogue partials alias dead f0hi region (after post-MMA sync)
constexpr int OFF_PART = OFF_F0HI;

__device__ __forceinline__ int swz(int px, int byte) {
    return px * 128 + (byte ^ ((px & 7) << 4));
}

__device__ __forceinline__ void mma16816(float* c, const unsigned* a,
                                         unsigned b0, unsigned b1) {
    asm volatile(
        "mma.sync.aligned.m16n8k16.row.col.f32.bf16.bf16.f32 "
        "{%0,%1,%2,%3}, {%4,%5,%6,%7}, {%8,%9}, {%0,%1,%2,%3};"
        : "+f"(c[0]), "+f"(c[1]), "+f"(c[2]), "+f"(c[3])
        : "r"(a[0]), "r"(a[1]), "r"(a[2]), "r"(a[3]), "r"(b0), "r"(b1));
}

// Convert 8 fp32 (one ch-octet of one pixel) to hi/lo bf16, write 16B each.
__device__ __forceinline__ void stage_unit(char* smem, const float* __restrict__ f0g,
                                           const float* __restrict__ f1g,
                                           int base, int y0, int u) {
    const int slot = u >> 3, oct = u & 7;
    const float* src;
    int pxi, aHi, aLo;
    if (slot < 440) {                     // f1: 10 rows x 44 cols
        const int row = slot / 44, x = slot - row * 44;
        const int gy = y0 - RADIUS + row;
        if ((unsigned)gy >= (unsigned)H_) return;   // junk rows: dy masked
        src = f1g + base + gy * W_ + x;
        pxi = row * F1PX + x + RADIUS;
        aHi = OFF_F1HI; aLo = OFF_F1LO;
    } else {                              // f0: 4 rows x 44 cols
        const int t = slot - 440;
        const int row = t / 44, x = t - row * 44;
        src = f0g + base + (y0 + row) * W_ + x;
        pxi = row * F0PX + x;
        aHi = OFF_F0HI; aLo = OFF_F0LO;
    }
    const int chb = oct * 8;
    float v[8];
    #pragma unroll
    for (int j = 0; j < 8; ++j) v[j] = src[(chb + j) * SP_];
    unsigned hw[4], lw[4];
    #pragma unroll
    for (int j = 0; j < 4; ++j) {
        const float v0 = v[2 * j], v1 = v[2 * j + 1];
        const __nv_bfloat16 h0 = __float2bfloat16(v0);
        const __nv_bfloat16 h1 = __float2bfloat16(v1);
        const __nv_bfloat16 l0 = __float2bfloat16(v0 - __bfloat162float(h0));
        const __nv_bfloat16 l1 = __float2bfloat16(v1 - __bfloat162float(h1));
        hw[j] = (unsigned)__bfloat16_as_ushort(h0) |
                ((unsigned)__bfloat16_as_ushort(h1) << 16);
        lw[j] = (unsigned)__bfloat16_as_ushort(l0) |
                ((unsigned)__bfloat16_as_ushort(l1) << 16);
    }
    *(uint4*)(smem + aHi + swz(pxi, oct * 16)) = make_uint4(hw[0], hw[1], hw[2], hw[3]);
    *(uint4*)(smem + aLo + swz(pxi, oct * 16)) = make_uint4(lw[0], lw[1], lw[2], lw[3]);
}

__global__ __launch_bounds__(NTHREADS, 1)
void flow_kernel(const float* __restrict__ f0g, const float* __restrict__ f1g,
                 float* __restrict__ outg) {
    extern __shared__ char smem[];
    const int tid  = threadIdx.x;
    const int y0   = blockIdx.x * TILE_Y;
    const int b    = blockIdx.y;
    const int ni   = b >> 2;
    const int si   = b & 3;
    const int base = ((ni * C_) * S_ + si) * P_;

    // ---------------- staging: 616 px-slots x 8 ch-octets -------------------
    for (int u = tid; u < 4928; u += NTHREADS)
        stage_unit(smem, f0g, f1g, base, y0, u);
    __syncthreads();

    // ------- MMA phase: warp = (dyset, row yl, 16-px strip); 24 warps -------
    {
        const int wid  = tid >> 5, lane = tid & 31;
        const int dyset = (wid >= 12);
        const int sub  = wid - (dyset ? 12 : 0);
        const int yl   = sub / 3, strip = sub % 3, xs = strip * 16;
        const int g    = lane >> 2;          // m-row / n within tile
        const int t4   = lane & 3;           // k-pair selector

        // Preload A-hi fragments only (register diet for 24 warps).
        unsigned ahi[4][4];
        const int apx = yl * F0PX + xs;
        #pragma unroll
        for (int kc = 0; kc < 4; ++kc) {
            const int by = kc * 32 + t4 * 4;
            ahi[kc][0] = *(const unsigned*)(smem + OFF_F0HI + swz(apx + g,     by));
            ahi[kc][1] = *(const unsigned*)(smem + OFF_F0HI + swz(apx + g + 8, by));
            ahi[kc][2] = *(const unsigned*)(smem + OFF_F0HI + swz(apx + g,     by + 16));
            ahi[kc][3] = *(const unsigned*)(smem + OFF_F0HI + swz(apx + g + 8, by + 16));
        }

        const int dyA = dyset ? 4 : 0;
        const int dyB = dyset ? 7 : 4;
        for (int dy = dyA; dy < dyB; ++dy) {
            const int gyr = y0 + yl + dy - RADIUS;
            if ((unsigned)gyr >= (unsigned)H_) continue;   // taps stay junk; masked
            const int row = yl + dy;                        // f1 smem row 0..9

            float acc[3][4];
            #pragma unroll
            for (int tt = 0; tt < 3; ++tt)
                #pragma unroll
                for (int r = 0; r < 4; ++r) acc[tt][r] = 0.0f;

            #pragma unroll
            for (int kc = 0; kc < 4; ++kc) {
                const int by = kc * 32 + t4 * 4;
                // B-hi for the 3 n-tiles (reused by hi*hi and lo*hi)
                unsigned bh[3][2];
                #pragma unroll
                for (int tt = 0; tt < 3; ++tt) {
                    const int pxb = row * F1PX + xs + 8 * tt + g;
                    bh[tt][0] = *(const unsigned*)(smem + OFF_F1HI + swz(pxb, by));
                    bh[tt][1] = *(const unsigned*)(smem + OFF_F1HI + swz(pxb, by + 16));
                }
                #pragma unroll
                for (int tt = 0; tt < 3; ++tt)
                    mma16816(acc[tt], ahi[kc], bh[tt][0], bh[tt][1]);   // hi*hi
                // A-lo for this kc (loaded on the fly)
                unsigned alo[4];
                alo[0] = *(const unsigned*)(smem + OFF_F0LO + swz(apx + g,     by));
                alo[1] = *(const unsigned*)(smem + OFF_F0LO + swz(apx + g + 8, by));
                alo[2] = *(const unsigned*)(smem + OFF_F0LO + swz(apx + g,     by + 16));
                alo[3] = *(const unsigned*)(smem + OFF_F0LO + swz(apx + g + 8, by + 16));
                #pragma unroll
                for (int tt = 0; tt < 3; ++tt)
                    mma16816(acc[tt], alo, bh[tt][0], bh[tt][1]);       // lo*hi
                #pragma unroll
                for (int tt = 0; tt < 3; ++tt) {                        // hi*lo
                    const int pxb = row * F1PX + xs + 8 * tt + g;
                    const unsigned bl0 = *(const unsigned*)(smem + OFF_F1LO + swz(pxb, by));
                    const unsigned bl1 = *(const unsigned*)(smem + OFF_F1LO + swz(pxb, by + 16));
                    mma16816(acc[tt], ahi[kc], bl0, bl1);
                }
            }

            // scatter the 7-diagonal band into taps[px][49]
            #pragma unroll
            for (int tt = 0; tt < 3; ++tt) {
                const int n0 = xs - RADIUS + 8 * tt + 2 * t4;
                #pragma unroll
                for (int cr = 0; cr < 4; ++cr) {
                    const int mrow = g + ((cr >= 2) ? 8 : 0);
                    const int px_x = xs + mrow;
                    const int n_x  = n0 + (cr & 1);
                    const int dx3  = n_x - px_x + RADIUS;
                    if (px_x < W_ && (unsigned)dx3 < 7u) {
                        *(float*)(smem + OFF_TAPS +
                                  (((yl * W_ + px_x) * 49) + dy * 7 + dx3) * 4) = acc[tt][cr];
                    }
                }
            }
        }
    }
    __syncthreads();

    // -------- epilogue pass 1: split taps 25/24 across 2 threads/px ---------
    if (tid < 352) {
        const int px   = tid >> 1;
        const int half = tid & 1;
        const int yl   = px / W_;
        const int x    = px - yl * W_;
        const int gy   = y0 + yl;
        const float* tp = (const float*)(smem + OFF_TAPS) + px * 49;

        float m = -1e30f, s = 0.0f, fx = 0.0f, fy = 0.0f;
        const int k0 = half ? 25 : 0;
        const int k1 = half ? 49 : 25;
        #pragma unroll 25
        for (int k = k0; k < k1; ++k) {
            const int dy = k / 7 - RADIUS, dx = k % 7 - RADIUS;
            const bool v = ((unsigned)(gy + dy) < (unsigned)H_) &&
                           ((unsigned)(x + dx) < (unsigned)W_);
            if (v) m = fmaxf(m, tp[k]);
        }
        #pragma unroll 25
        for (int k = k0; k < k1; ++k) {
            const int dy = k / 7 - RADIUS, dx = k % 7 - RADIUS;
            const bool v = ((unsigned)(gy + dy) < (unsigned)H_) &&
                           ((unsigned)(x + dx) < (unsigned)W_);
            const float e = v ? __expf((tp[k] - m) * 0.125f) : 0.0f;
            s  += e;
            fx += e * (float)dx;
            fy += e * (float)dy;
        }
        ((float4*)(smem + OFF_PART))[tid] = make_float4(m, s, fx, fy);
    }
    __syncthreads();

    // -------- epilogue pass 2: combine halves, write flow -------------------
    if (tid < 176) {
        const int yl = tid / W_;
        const int x  = tid - yl * W_;
        const float4 p0 = ((const float4*)(smem + OFF_PART))[2 * tid];
        const float4 p1 = ((const float4*)(smem + OFF_PART))[2 * tid + 1];
        const float M  = fmaxf(p0.x, p1.x);          // center tap (half0) always valid
        const float w0 = __expf((p0.x - M) * 0.125f);
        const float w1 = __expf((p1.x - M) * 0.125f);  // m=-1e30 -> 0, s already 0
        const float S  = p0.y * w0 + p1.y * w1;
        const float FX = p0.z * w0 + p1.z * w1;
        const float FY = p0.w * w0 + p1.w * w1;
        const float inv = 1.0f / S;
        const int ob = ((ni * 2) * S_ + si) * P_ + (y0 + yl) * W_ + x;
        outg[ob]       = FX * inv;
        outg[ob + SP_] = FY * inv;
    }
}

extern "C" void kernel_launch(void* const* d_in, const int* in_sizes, int n_in,
                              void* d_out, int out_size) {
    const float* f0 = (const float*)d_in[0];
    const float* f1 = (const float*)d_in[1];
    float* out = (float*)d_out;

    cudaFuncSetAttribute(flow_kernel,
                         cudaFuncAttributeMaxDynamicSharedMemorySize, SMEM_BYTES);

    dim3 grid(H_ / TILE_Y, N_ * S_);
    flow_kernel<<<grid, NTHREADS, SMEM_BYTES>>>(f0, f1, out);
}

// round 11
// speedup vs baseline: 1.2076x; 1.2076x over previous
#include <cuda_runtime.h>

// Shapes fixed by setup_inputs
#define RADIUS 3
constexpr int N_ = 2, C_ = 64, S_ = 4, H_ = 64, W_ = 44;
constexpr int P_  = H_ * W_;
constexpr int SP_ = S_ * P_;                   // 11264 (channel stride)

constexpr int TILE_Y  = 4;
constexpr int ROWS_SM = 10;
constexpr int WPAD    = 54;   // odd ull-count rows -> conflict-free tap LDS.64 (R4-R6 proven)
constexpr int W0PAD   = 48;   // f0: clean LDS.128
constexpr int NPIX    = 176;
constexpr int NTHREADS = 896;                  // 28 warps
constexpr int NACT    = 7 * 44;                // 308 active threads per half

constexpr int CHUNK   = 16;                    // channels per pipeline stage
constexpr int F1C = CHUNK * ROWS_SM * WPAD;    // 8640 floats per f1 buffer
constexpr int F0C = CHUNK * TILE_Y * W0PAD;    // 3072 floats per f0 buffer
constexpr int OFF_F0 = 2 * F1C;                // 17280 (floats)
// exchange + reduction live AFTER staging (no aliasing)
constexpr int BYTE_EX   = (2 * F1C + 2 * F0C) * 4;     // 93696
constexpr int BYTE_EXA0 = BYTE_EX;                     // ull[6][308]  h1 -> h0 (px0,1)
constexpr int BYTE_EXA1 = BYTE_EXA0 + 6 * NACT * 8;    // ull[6][308]  h0 -> h1 (px2,3)
constexpr int BYTE_EXS0 = BYTE_EXA1 + 6 * NACT * 8;    // float2[308]
constexpr int BYTE_EXS1 = BYTE_EXS0 + NACT * 8;
constexpr int BYTE_RED  = BYTE_EXS1 + NACT * 8;        // float4[7][176]
constexpr int SMEM_BYTES = BYTE_RED + 7 * NPIX * 16;   // 147904

using ull = unsigned long long;

__device__ __forceinline__ ull pkdup(float a) {
    ull r; asm("mov.b64 %0, {%1, %1};" : "=l"(r) : "f"(a)); return r;
}
__device__ __forceinline__ void upk(float& lo, float& hi, ull v) {
    asm("mov.b64 {%0, %1}, %2;" : "=f"(lo), "=f"(hi) : "l"(v));
}
__device__ __forceinline__ void fma2(ull& d, ull a, ull b) {
    asm("fma.rn.f32x2 %0, %1, %2, %0;" : "+l"(d) : "l"(a), "l"(b));
}
__device__ __forceinline__ void add2(ull& d, ull a) {
    asm("add.rn.f32x2 %0, %0, %1;" : "+l"(d) : "l"(a));
}
__device__ __forceinline__ void cpa4(unsigned dst, const float* src) {
    asm volatile("cp.async.ca.shared.global [%0], [%1], 4;" :: "r"(dst), "l"(src));
}
__device__ __forceinline__ void cpa16(unsigned dst, const float* src) {
    asm volatile("cp.async.cg.shared.global [%0], [%1], 16;" :: "r"(dst), "l"(src));
}

// Stage one 16-channel chunk into buffer pb via cp.async (no registers held).
__device__ __forceinline__ void stage_chunk(unsigned smb,
                                            const float* __restrict__ f0g,
                                            const float* __restrict__ f1g,
                                            int base1, int y0, int ck, int pb, int tid) {
    const int chb = ck * CHUNK;
    // f1: 16 ch x 10 rows x 44 cols, 4B each (odd smem col base 3)
    #pragma unroll
    for (int it = 0; it < 8; ++it) {
        const int slot = tid + it * NTHREADS;
        if (slot < 7040) {
            const int ch  = slot / 440;
            const int rem = slot - ch * 440;
            const int row = rem / 44;
            const int col = rem - row * 44;
            const int gy  = y0 - RADIUS + row;
            if ((unsigned)gy < (unsigned)H_) {
                cpa4(smb + (pb * F1C + (ch * ROWS_SM + row) * WPAD + 3 + col) * 4,
                     f1g + base1 + (chb + ch) * SP_ + gy * W_ + col);
            }
        }
    }
    // f0: 16 ch x 4 rows x 11 x 16B (row = 44 floats = 11 x float4, 16B aligned)
    if (tid < 704) {
        const int ch  = tid / 44;
        const int rem = tid - ch * 44;
        const int row = rem / 11;
        const int c16 = rem - row * 11;
        cpa16(smb + (OFF_F0 + pb * F0C + (ch * TILE_Y + row) * W0PAD + c16 * 4) * 4,
              f0g + base1 + (chb + ch) * SP_ + (y0 + row) * W_ + c16 * 4);
    }
}

__global__ __launch_bounds__(NTHREADS, 1)
void flow_kernel(const float* __restrict__ f0g, const float* __restrict__ f1g,
                 float* __restrict__ outg) {
    extern __shared__ float sm[];
    char* smc = reinterpret_cast<char*>(sm);
    unsigned smb;
    asm("{ .reg .u64 t; cvta.to.shared.u64 t, %1; cvt.u32.u64 %0, t; }"
        : "=r"(smb) : "l"(sm));

    ull*    exA0 = reinterpret_cast<ull*>(smc + BYTE_EXA0);
    ull*    exA1 = reinterpret_cast<ull*>(smc + BYTE_EXA1);
    float2* exS0 = reinterpret_cast<float2*>(smc + BYTE_EXS0);
    float2* exS1 = reinterpret_cast<float2*>(smc + BYTE_EXS1);
    float4* red4 = reinterpret_cast<float4*>(smc + BYTE_RED);

    const int tid  = threadIdx.x;
    const int grp  = tid >> 6;           // 0..13
    const int s    = tid & 63;
    const int h    = grp / 7;            // channel sub-half within each chunk
    const int g    = grp % 7;            // tap row, dy = g-3
    int yl, qx;
    if (s < 32) { yl = s >> 3;       qx = s & 7; }
    else        { int l = s - 32; yl = l / 3; qx = 8 + l % 3; }
    const bool active = (s < 44);

    const int y0   = blockIdx.x * TILE_Y;
    const int b    = blockIdx.y;
    const int ni   = b >> 2;
    const int si   = b & 3;
    const int base1 = ((ni * C_) * S_ + si) * P_;

    // ---- kick off chunk 0 DMA immediately ----
    stage_chunk(smb, f0g, f1g, base1, y0, 0, 0, tid);
    asm volatile("cp.async.commit_group;" ::: "memory");

    // ---- halo zeroing (both buffers, once; DMA never touches halo) ----
    for (int i = tid; i < 2 * CHUNK * ROWS_SM * 6; i += NTHREADS) {
        const int bb = i / 960;
        const int r  = i - bb * 960;
        const int ch = r / 60;
        const int rr = r - ch * 60;
        const int row = rr / 6;
        const int c6  = rr - row * 6;
        const int col = (c6 < 3) ? c6 : (44 + c6);
        sm[bb * F1C + (ch * ROWS_SM + row) * WPAD + col] = 0.0f;
    }
    if (y0 == 0 || y0 == H_ - TILE_Y) {
        const int r0 = (y0 == 0) ? 0 : 7;
        for (int i = tid; i < 2 * CHUNK * 3 * 44; i += NTHREADS) {
            const int bb = i / 2112;
            const int r  = i - bb * 2112;
            const int ch = r / 132;
            const int rr = r - ch * 132;
            const int row = rr / 44;
            const int col = rr - row * 44;
            sm[bb * F1C + (ch * ROWS_SM + r0 + row) * WPAD + 3 + col] = 0.0f;
        }
    }

    // ---- pipelined main loop: compute chunk ck while DMA fills ck+1 ----
    ull   accP[12];
    float accS[4];
    #pragma unroll
    for (int i = 0; i < 12; ++i) accP[i] = 0ull;
    #pragma unroll
    for (int i = 0; i < 4; ++i) accS[i] = 0.0f;

    #pragma unroll
    for (int ck = 0; ck < 4; ++ck) {
        if (ck < 3) {
            stage_chunk(smb, f0g, f1g, base1, y0, ck + 1, (ck + 1) & 1, tid);
            asm volatile("cp.async.commit_group;" ::: "memory");
            asm volatile("cp.async.wait_group 1;" ::: "memory");
        } else {
            asm volatile("cp.async.wait_group 0;" ::: "memory");
        }
        __syncthreads();                  // chunk ck visible to all

        if (active) {
            const int pb = ck & 1;
            const ull* __restrict__ tap =
                reinterpret_cast<const ull*>(sm + pb * F1C) +
                ((h * 8) * ROWS_SM + yl + g) * (WPAD / 2) + 2 * qx;
            const float4* __restrict__ a4 =
                reinterpret_cast<const float4*>(sm + OFF_F0 + pb * F0C) +
                ((h * 8) * TILE_Y + yl) * (W0PAD / 4) + qx;

            #pragma unroll 2
            for (int c = 0; c < 8; ++c) {
                const ull P0 = tap[0], P2 = tap[1], P4 = tap[2], P6 = tap[3], P8 = tap[4];
                const float4 A = a4[0];
                const ull aa0 = pkdup(A.x), aa1 = pkdup(A.y),
                          aa2 = pkdup(A.z), aa3 = pkdup(A.w);
                float t0lo, t0hi, t1lo, t1hi, t3lo, t3hi, t4lo, t4hi;
                upk(t0lo, t0hi, P0);
                upk(t1lo, t1hi, P2);
                upk(t3lo, t3hi, P6);
                upk(t4lo, t4hi, P8);

                fma2(accP[0],  aa0, P0);  fma2(accP[1],  aa0, P2);
                fma2(accP[2],  aa0, P4);
                fma2(accP[3],  aa1, P2);  fma2(accP[4],  aa1, P4);
                fma2(accP[5],  aa1, P6);
                fma2(accP[6],  aa2, P2);  fma2(accP[7],  aa2, P4);
                fma2(accP[8],  aa2, P6);
                fma2(accP[9],  aa3, P4);  fma2(accP[10], aa3, P6);
                fma2(accP[11], aa3, P8);
                accS[0] = fmaf(A.x, t3lo, accS[0]);
                accS[1] = fmaf(A.y, t0hi, accS[1]);
                accS[2] = fmaf(A.z, t4lo, accS[2]);
                accS[3] = fmaf(A.w, t1hi, accS[3]);

                tap += ROWS_SM * (WPAD / 2);
                a4  += TILE_Y * (W0PAD / 4);
            }
        }
        __syncthreads();                  // buffer pb free for reuse
    }

    // ---- symmetric exchange: h0 finishes px0,1 ; h1 finishes px2,3 ----
    const int widx = g * 44 + s;          // s < 44 when active -> no collisions
    if (active) {
        if (h == 0) {
            #pragma unroll
            for (int j = 0; j < 6; ++j) exA1[j * NACT + widx] = accP[6 + j];
            exS1[widx] = make_float2(accS[2], accS[3]);
        } else {
            #pragma unroll
            for (int j = 0; j < 6; ++j) exA0[j * NACT + widx] = accP[j];
            exS0[widx] = make_float2(accS[0], accS[1]);
        }
    }
    __syncthreads();

    if (active) {
        float acc[2][7];
        int pxa;
        if (h == 0) {
            #pragma unroll
            for (int j = 0; j < 6; ++j) add2(accP[j], exA0[j * NACT + widx]);
            const float2 e = exS0[widx];
            accS[0] += e.x; accS[1] += e.y;
            upk(acc[0][0], acc[0][1], accP[0]);
            upk(acc[0][2], acc[0][3], accP[1]);
            upk(acc[0][4], acc[0][5], accP[2]);  acc[0][6] = accS[0];
            acc[1][0] = accS[1];
            upk(acc[1][1], acc[1][2], accP[3]);
            upk(acc[1][3], acc[1][4], accP[4]);
            upk(acc[1][5], acc[1][6], accP[5]);
            pxa = 0;
        } else {
            #pragma unroll
            for (int j = 0; j < 6; ++j) add2(accP[6 + j], exA1[j * NACT + widx]);
            const float2 e = exS1[widx];
            accS[2] += e.x; accS[3] += e.y;
            upk(acc[0][0], acc[0][1], accP[6]);
            upk(acc[0][2], acc[0][3], accP[7]);
            upk(acc[0][4], acc[0][5], accP[8]);  acc[0][6] = accS[2];
            acc[1][0] = accS[3];
            upk(acc[1][1], acc[1][2], accP[9]);
            upk(acc[1][3], acc[1][4], accP[10]);
            upk(acc[1][5], acc[1][6], accP[11]);
            pxa = 2;
        }
        const bool rowv = ((unsigned)(y0 + yl + g - RADIUS) < (unsigned)H_);
        #pragma unroll
        for (int p = 0; p < 2; ++p) {
            const int xl = 4 * qx + pxa + p;
            float m = -1e30f;
            #pragma unroll
            for (int d = 0; d < 7; ++d) {
                const bool v = rowv && ((unsigned)(xl + d - RADIUS) < (unsigned)W_);
                if (v) m = fmaxf(m, acc[p][d]);
            }
            float ss = 0.0f, fx = 0.0f;
            #pragma unroll
            for (int d = 0; d < 7; ++d) {
                const bool v = rowv && ((unsigned)(xl + d - RADIUS) < (unsigned)W_);
                const float e = v ? __expf((acc[p][d] - m) * 0.125f) : 0.0f;
                ss += e;
                fx += e * (float)(d - RADIUS);
            }
            red4[g * NPIX + yl * W_ + xl] = make_float4(m, ss, fx, 0.0f);
        }
    }
    __syncthreads();

    // ---- combine 7 row-partials per pixel ----
    if (tid < NPIX) {
        const int xl = tid % W_;
        const int yr = tid / W_;

        float4 p[7];
        #pragma unroll
        for (int gg = 0; gg < 7; ++gg) p[gg] = red4[gg * NPIX + tid];

        float M = p[0].x;
        #pragma unroll
        for (int gg = 1; gg < 7; ++gg) M = fmaxf(M, p[gg].x);

        float S = 0.0f, FX = 0.0f, FY = 0.0f;
        #pragma unroll
        for (int gg = 0; gg < 7; ++gg) {
            const float wg = __expf((p[gg].x - M) * 0.125f);  // empty row -> 0
            S  += p[gg].y * wg;
            FX += p[gg].z * wg;
            FY += p[gg].y * wg * (float)(gg - RADIUS);
        }
        const float inv = 1.0f / S;
        const int ob = ((ni * 2) * S_ + si) * P_ + (y0 + yr) * W_ + xl;
        outg[ob]       = FX * inv;
        outg[ob + SP_] = FY * inv;
    }
}

extern "C" void kernel_launch(void* const* d_in, const int* in_sizes, int n_in,
                              void* d_out, int out_size) {
    const float* f0 = (const float*)d_in[0];
    const float* f1 = (const float*)d_in[1];
    float* out = (float*)d_out;

    cudaFuncSetAttribute(flow_kernel,
                         cudaFuncAttributeMaxDynamicSharedMemorySize, SMEM_BYTES);

    dim3 grid(H_ / TILE_Y, N_ * S_);
    flow_kernel<<<grid, NTHREADS, SMEM_BYTES>>>(f0, f1, out);
}

// round 12
// speedup vs baseline: 1.3361x; 1.1064x over previous
#include <cuda_runtime.h>

// Shapes fixed by setup_inputs
#define RADIUS 3
constexpr int N_ = 2, C_ = 64, S_ = 4, H_ = 64, W_ = 44;
constexpr int P_  = H_ * W_;
constexpr int SP_ = S_ * P_;                  // 11264 (channel stride)

constexpr int TILE_Y  = 4;
constexpr int ROWS_SM = 10;
constexpr int SLOTS   = 50;                   // ull-cols per row; f1 slot = x+3
constexpr int ROWF    = 100;                  // floats per row = 25 float4 (ODD -> bank-tiling)
constexpr int NTHREADS = 448;                 // 7 tap-row groups x 64
constexpr int NPIX    = 176;

constexpr int F1_FL  = 32 * ROWS_SM * ROWF;   // 32000 floats
constexpr int F0_FL  = 32 * TILE_Y * ROWF;    // 12800 floats
constexpr int RED_FL = F1_FL + F0_FL;         // 44800
constexpr int SMEM_BYTES = (RED_FL + 7 * NPIX * 4) * 4;   // 198912

using ull = unsigned long long;

__device__ __forceinline__ void fma2(ull& d, ull a, ull b) {
    asm("fma.rn.f32x2 %0, %1, %2, %0;" : "+l"(d) : "l"(a), "l"(b));
}
__device__ __forceinline__ void upk(float& lo, float& hi, ull v) {
    asm("mov.b64 {%0, %1}, %2;" : "=f"(lo), "=f"(hi) : "l"(v));
}

__global__ __launch_bounds__(NTHREADS, 1)
void flow_kernel(const float* __restrict__ f0g, const float* __restrict__ f1g,
                 float* __restrict__ outg) {
    extern __shared__ float sm[];
    float* f1s = sm;                   // [32 cpair][10 row][50 slot][2ch]
    float* f0s = sm + F1_FL;           // [32 cpair][4 yl][50 px-slot][2ch]
    float4* red4 = reinterpret_cast<float4*>(sm + RED_FL);   // [7][176]

    const int tid  = threadIdx.x;
    const int y0   = blockIdx.x * TILE_Y;
    const int b    = blockIdx.y;
    const int ni   = b >> 2;
    const int si   = b & 3;
    const int base1 = ((ni * C_) * S_ + si) * P_;

    // ============ staging: channel-interleaved tiles, 16B global loads ======
    if (tid < 320) {                   // f1 units: (cpair, row)
        const int cp  = tid / 10;
        const int row = tid - cp * 10;
        const int gy  = y0 - RADIUS + row;
        float* dst = f1s + (cp * ROWS_SM + row) * ROWF;
        if ((unsigned)gy < (unsigned)H_) {
            const float* s0 = f1g + base1 + (2 * cp) * SP_ + gy * W_;
            const float* s1 = s0 + SP_;
            #pragma unroll
            for (int k = 0; k < 11; ++k) {
                const float4 a = *(const float4*)(s0 + 4 * k);
                const float4 v = *(const float4*)(s1 + 4 * k);
                float2* d2 = (float2*)(dst + 2 * (4 * k + 3));
                d2[0] = make_float2(a.x, v.x);
                d2[1] = make_float2(a.y, v.y);
                d2[2] = make_float2(a.z, v.z);
                d2[3] = make_float2(a.w, v.w);
            }
            // halo slots 0,1,2 and 47,48,49
            float2* dz = (float2*)dst;
            dz[0] = dz[1] = dz[2] = make_float2(0.f, 0.f);
            dz[47] = dz[48] = dz[49] = make_float2(0.f, 0.f);
        } else {
            float4* dz = (float4*)dst;
            #pragma unroll
            for (int k = 0; k < 25; ++k) dz[k] = make_float4(0.f, 0.f, 0.f, 0.f);
        }
    } else {                           // f0 units: (cpair, yl) -- exactly 128
        const int t  = tid - 320;
        const int cp = t >> 2;
        const int yl = t & 3;
        const float* s0 = f0g + base1 + (2 * cp) * SP_ + (y0 + yl) * W_;
        const float* s1 = s0 + SP_;
        float* dst = f0s + (cp * TILE_Y + yl) * ROWF;
        #pragma unroll
        for (int k = 0; k < 11; ++k) {
            const float4 a = *(const float4*)(s0 + 4 * k);
            const float4 v = *(const float4*)(s1 + 4 * k);
            float2* d2 = (float2*)(dst + 2 * (4 * k));
            d2[0] = make_float2(a.x, v.x);
            d2[1] = make_float2(a.y, v.y);
            d2[2] = make_float2(a.z, v.z);
            d2[3] = make_float2(a.w, v.w);
        }
        // f0 pad slots 44..49 never read (max px slot read = 43)
    }
    __syncthreads();

    // ============ main loop: 4 px x 7 taps x 32 ch-pairs ====================
    // lane map: q = b4*4 + b1b0 (+8 per half-warp-pair), yl = b2 + 2*b3
    // -> every 8-lane LDS.128 phase tiles banks (odd 25-f4 row stride).
    const int g  = tid >> 6;           // tap row, dy = g-3
    const int s  = tid & 63;
    const int l  = s & 31;
    const int hw = s >> 5;
    const int q  = hw * 8 + (((l >> 4) & 1) << 2) + (l & 3);   // x-quad 0..15
    const int yl = ((l >> 2) & 1) + (((l >> 3) & 1) << 1);
    const bool active = (q < 11);

    ull acc2[28];                      // [p][d]: (even-ch sum, odd-ch sum)
    #pragma unroll
    for (int i = 0; i < 28; ++i) acc2[i] = 0ull;

    if (active) {
        const ull* tap = (const ull*)f1s + (yl + g) * SLOTS + 4 * q;
        const ull* a2  = (const ull*)f0s + yl * SLOTS + 4 * q;

        #pragma unroll 2
        for (int cp = 0; cp < 32; ++cp) {
            const ulonglong2 L0 = *(const ulonglong2*)(tap + 0);
            const ulonglong2 L1 = *(const ulonglong2*)(tap + 2);
            const ulonglong2 L2 = *(const ulonglong2*)(tap + 4);
            const ulonglong2 L3 = *(const ulonglong2*)(tap + 6);
            const ulonglong2 L4 = *(const ulonglong2*)(tap + 8);
            const ulonglong2 A01 = *(const ulonglong2*)(a2 + 0);
            const ulonglong2 A23 = *(const ulonglong2*)(a2 + 2);
            const ull U[10] = {L0.x, L0.y, L1.x, L1.y, L2.x,
                               L2.y, L3.x, L3.y, L4.x, L4.y};
            const ull A[4]  = {A01.x, A01.y, A23.x, A23.y};
            #pragma unroll
            for (int p = 0; p < 4; ++p)
                #pragma unroll
                for (int d = 0; d < 7; ++d)
                    fma2(acc2[p * 7 + d], A[p], U[p + d]);
            tap += ROWS_SM * SLOTS;    // 500
            a2  += TILE_Y * SLOTS;     // 200
        }
    }

    // ============ stats: merge ch-halves, masked row softmax ================
    if (active) {
        const bool rowv = ((unsigned)(y0 + yl + g - RADIUS) < (unsigned)H_);
        #pragma unroll
        for (int p = 0; p < 4; ++p) {
            const int x = 4 * q + p;           // 0..43, all valid
            float a[7];
            #pragma unroll
            for (int d = 0; d < 7; ++d) {
                float lo, hi;
                upk(lo, hi, acc2[p * 7 + d]);
                a[d] = lo + hi;
            }
            float m = -1e30f;
            #pragma unroll
            for (int d = 0; d < 7; ++d) {
                const bool v = rowv && ((unsigned)(x + d - RADIUS) < (unsigned)W_);
                if (v) m = fmaxf(m, a[d]);
            }
            float ss = 0.0f, fx = 0.0f;
            #pragma unroll
            for (int d = 0; d < 7; ++d) {
                const bool v = rowv && ((unsigned)(x + d - RADIUS) < (unsigned)W_);
                const float e = v ? __expf((a[d] - m) * 0.125f) : 0.0f;
                ss += e;
                fx += e * (float)(d - RADIUS);
            }
            red4[g * NPIX + yl * W_ + x] = make_float4(m, ss, fx, 0.0f);
        }
    }
    __syncthreads();

    // ============ combine 7 row-partials per pixel ==========================
    if (tid < NPIX) {
        const int xl = tid % W_;
        const int yr = tid / W_;

        float4 p[7];
        #pragma unroll
        for (int gg = 0; gg < 7; ++gg) p[gg] = red4[gg * NPIX + tid];

        float M = p[0].x;
        #pragma unroll
        for (int gg = 1; gg < 7; ++gg) M = fmaxf(M, p[gg].x);

        float S = 0.0f, FX = 0.0f, FY = 0.0f;
        #pragma unroll
        for (int gg = 0; gg < 7; ++gg) {
            const float wg = __expf((p[gg].x - M) * 0.125f);   // empty row -> 0
            S  += p[gg].y * wg;
            FX += p[gg].z * wg;
            FY += p[gg].y * wg * (float)(gg - RADIUS);
        }
        const float inv = 1.0f / S;
        const int ob = ((ni * 2) * S_ + si) * P_ + (y0 + yr) * W_ + xl;
        outg[ob]       = FX * inv;
        outg[ob + SP_] = FY * inv;
    }
}

extern "C" void kernel_launch(void* const* d_in, const int* in_sizes, int n_in,
                              void* d_out, int out_size) {
    const float* f0 = (const float*)d_in[0];
    const float* f1 = (const float*)d_in[1];
    float* out = (float*)d_out;

    cudaFuncSetAttribute(flow_kernel,
                         cudaFuncAttributeMaxDynamicSharedMemorySize, SMEM_BYTES);

    dim3 grid(H_ / TILE_Y, N_ * S_);
    flow_kernel<<<grid, NTHREADS, SMEM_BYTES>>>(f0, f1, out);
}

// round 13
// speedup vs baseline: 1.4785x; 1.1065x over previous
#include <cuda_runtime.h>

// Shapes fixed by setup_inputs
#define RADIUS 3
constexpr int N_ = 2, C_ = 64, S_ = 4, H_ = 64, W_ = 44;
constexpr int P_  = H_ * W_;
constexpr int SP_ = S_ * P_;                  // 11264 (channel stride)

constexpr int TILE_Y  = 4;
constexpr int ROWS_SM = 10;
constexpr int ROWF    = 100;   // floats per (cpair,row) = 25 float4 (ODD -> bank tiling)
constexpr int NTHREADS = 672;  // 7 tap-row groups x 96 (21 warps)
constexpr int NPIX    = 176;

constexpr int F1_FL = 32 * ROWS_SM * ROWF;    // 32000 floats
constexpr int F0_FL = 32 * TILE_Y * ROWF;     // 12800 floats
constexpr int SMEM_BYTES = (F1_FL + F0_FL + 7 * NPIX * 4) * 4;   // 198912

using ull = unsigned long long;

__device__ __forceinline__ void fma2(ull& d, ull a, ull b) {
    asm("fma.rn.f32x2 %0, %1, %2, %0;" : "+l"(d) : "l"(a), "l"(b));
}
__device__ __forceinline__ void upk(float& lo, float& hi, ull v) {
    asm("mov.b64 {%0, %1}, %2;" : "=f"(lo), "=f"(hi) : "l"(v));
}

__global__ __launch_bounds__(NTHREADS, 1)
void flow_kernel(const float* __restrict__ f0g, const float* __restrict__ f1g,
                 float* __restrict__ outg) {
    extern __shared__ float sm[];
    float* f1s = sm;                  // [32 cp][10 row][50 slot][2ch]; slot = gx+3
    float* f0s = sm + F1_FL;          // [32 cp][4 yl][50 slot][2ch]; slot = x
    float4* red4 = reinterpret_cast<float4*>(sm + F1_FL + F0_FL);   // [7][176]

    const int tid  = threadIdx.x;
    const int y0   = blockIdx.x * TILE_Y;
    const int b    = blockIdx.y;
    const int ni   = b >> 2;
    const int si   = b & 3;
    const int base1 = ((ni * C_) * S_ + si) * P_;

    // ======== staging: coalesced float4 loads, ch-interleaved stores ========
    // NO zero-fill anywhere: halo/OOB slots keep stale garbage; every garbage
    // tap is masked in the stats phase and never read (NaN-safe by masking).
    for (int u = tid; u < 4928; u += NTHREADS) {
        if (u < 3520) {                       // f1: (cp, row, k): 32*10*11
            const int cp  = u / 110;
            const int rem = u - cp * 110;
            const int row = rem / 11;
            const int k   = rem - row * 11;
            const int gy  = y0 - RADIUS + row;
            if ((unsigned)gy < (unsigned)H_) {
                const float* s0 = f1g + base1 + (2 * cp) * SP_ + gy * W_ + 4 * k;
                const float4 a = *(const float4*)s0;
                const float4 v = *(const float4*)(s0 + SP_);
                float2* d2 = (float2*)(f1s + (cp * ROWS_SM + row) * ROWF + 2 * (4 * k + 3));
                d2[0] = make_float2(a.x, v.x);
                d2[1] = make_float2(a.y, v.y);
                d2[2] = make_float2(a.z, v.z);
                d2[3] = make_float2(a.w, v.w);
            }
        } else {                              // f0: (cp, yl, k): 32*4*11
            const int t   = u - 3520;
            const int cp  = t / 44;
            const int rem = t - cp * 44;
            const int yl  = rem / 11;
            const int k   = rem - yl * 11;
            const float* s0 = f0g + base1 + (2 * cp) * SP_ + (y0 + yl) * W_ + 4 * k;
            const float4 a = *(const float4*)s0;
            const float4 v = *(const float4*)(s0 + SP_);
            float2* d2 = (float2*)(f0s + (cp * TILE_Y + yl) * ROWF + 2 * (4 * k));
            d2[0] = make_float2(a.x, v.x);
            d2[1] = make_float2(a.y, v.y);
            d2[2] = make_float2(a.z, v.z);
            d2[3] = make_float2(a.w, v.w);
        }
    }
    __syncthreads();

    // ======== main loop: 2 px x 7 taps x 32 ch-pairs, pure LDS.128 ==========
    // Group g (96 thr) = tap row dy = g-3. Lane map: q = wig*8 + (l&7) (x-pair
    // index, active q<22), yl = l>>3. Every 8-lane phase: fixed yl, 8
    // consecutive f4 addrs -> conflict-free.
    const int g   = tid / 96;
    const int s   = tid - g * 96;
    const int l   = s & 31;
    const int q   = (s >> 5) * 8 + (l & 7);
    const int yl  = l >> 3;
    const bool active = (q < 22);

    ull accA[7], accB[7];                     // px0 = 2q, px1 = 2q+1
    #pragma unroll
    for (int d = 0; d < 7; ++d) { accA[d] = 0ull; accB[d] = 0ull; }

    if (active) {
        // slots needed: [2q, 2q+7] = f4 indices q..q+3 (tap slot = x+d)
        const ulonglong2* __restrict__ tap =
            (const ulonglong2*)f1s + (yl + g) * 25 + q;
        const ulonglong2* __restrict__ a2 =
            (const ulonglong2*)f0s + yl * 25 + q;

        #pragma unroll 2
        for (int cp = 0; cp < 32; ++cp) {
            const ulonglong2 T0 = tap[0], T1 = tap[1], T2 = tap[2], T3 = tap[3];
            const ulonglong2 A  = a2[0];
            const ull U[8] = {T0.x, T0.y, T1.x, T1.y, T2.x, T2.y, T3.x, T3.y};
            #pragma unroll
            for (int d = 0; d < 7; ++d) fma2(accA[d], A.x, U[d]);
            #pragma unroll
            for (int d = 0; d < 7; ++d) fma2(accB[d], A.y, U[d + 1]);
            tap += 250;                       // 10 rows * 25 f4 per cpair
            a2  += 100;                       // 4 rows * 25 f4
        }
    }

    // ======== stats: merge ch-halves, masked per-row softmax ================
    if (active) {
        const bool rowv = ((unsigned)(y0 + yl + g - RADIUS) < (unsigned)H_);
        #pragma unroll
        for (int p = 0; p < 2; ++p) {
            const int x = 2 * q + p;          // 0..43
            const ull* acc = p ? accB : accA;
            float a[7];
            #pragma unroll
            for (int d = 0; d < 7; ++d) {
                float lo, hi;
                upk(lo, hi, acc[d]);
                a[d] = lo + hi;
            }
            float m = -1e30f;
            #pragma unroll
            for (int d = 0; d < 7; ++d) {
                const bool v = rowv && ((unsigned)(x + d - RADIUS) < (unsigned)W_);
                if (v) m = fmaxf(m, a[d]);
            }
            float ss = 0.0f, fx = 0.0f;
            #pragma unroll
            for (int d = 0; d < 7; ++d) {
                const bool v = rowv && ((unsigned)(x + d - RADIUS) < (unsigned)W_);
                const float e = v ? __expf((a[d] - m) * 0.125f) : 0.0f;
                ss += e;
                fx += e * (float)(d - RADIUS);
            }
            red4[g * NPIX + yl * W_ + x] = make_float4(m, ss, fx, 0.0f);
        }
    }
    __syncthreads();

    // ======== combine 7 row-partials per pixel ==============================
    if (tid < NPIX) {
        const int xl = tid % W_;
        const int yr = tid / W_;

        float4 p[7];
        #pragma unroll
        for (int gg = 0; gg < 7; ++gg) p[gg] = red4[gg * NPIX + tid];

        float M = p[0].x;
        #pragma unroll
        for (int gg = 1; gg < 7; ++gg) M = fmaxf(M, p[gg].x);

        float S = 0.0f, FX = 0.0f, FY = 0.0f;
        #pragma unroll
        for (int gg = 0; gg < 7; ++gg) {
            const float wg = __expf((p[gg].x - M) * 0.125f);   // empty row -> 0
            S  += p[gg].y * wg;
            FX += p[gg].z * wg;
            FY += p[gg].y * wg * (float)(gg - RADIUS);
        }
        const float inv = 1.0f / S;
        const int ob = ((ni * 2) * S_ + si) * P_ + (y0 + yr) * W_ + xl;
        outg[ob]       = FX * inv;
        outg[ob + SP_] = FY * inv;
    }
}

extern "C" void kernel_launch(void* const* d_in, const int* in_sizes, int n_in,
                              void* d_out, int out_size) {
    const float* f0 = (const float*)d_in[0];
    const float* f1 = (const float*)d_in[1];
    float* out = (float*)d_out;

    cudaFuncSetAttribute(flow_kernel,
                         cudaFuncAttributeMaxDynamicSharedMemorySize, SMEM_BYTES);

    dim3 grid(H_ / TILE_Y, N_ * S_);
    flow_kernel<<<grid, NTHREADS, SMEM_BYTES>>>(f0, f1, out);
}